// round 11
// baseline (speedup 1.0000x reference)
#include <cuda_runtime.h>

#define BSZ 64
#define ICAPS 8192
#define JCAPS 8
#define NDIM 8
#define MDIM 16

#define CI 8
#define NCHUNKS (ICAPS / CI)       /* 1024 */
#define THREADS 1024

#define W_FLOATS (CI * 1024)       /* 8192 per buffer: [ci][n][j^(n&1)][m16] */
#define X_STRIDE 68                /* non-duplicated x row: 64 data + 4 pad */
#define X_FLOATS (BSZ * X_STRIDE)  /* 4352 */
#define SMEM_FLOATS (2 * W_FLOATS + X_FLOATS)       /* 20736 */
#define SMEM_BYTES (SMEM_FLOATS * 4)                /* 82944 B */

__device__ float g_s[3][BSZ * JCAPS * MDIM];   // stage-wise s accumulators
__device__ float g_dummy[32];

typedef unsigned long long u64;

__device__ __forceinline__ u64 pk2(float a, float b) {
    u64 r; asm("mov.b64 %0, {%1, %2};" : "=l"(r) : "f"(a), "f"(b)); return r;
}
__device__ __forceinline__ void upk2(u64 v, float& a, float& b) {
    asm("mov.b64 {%0, %1}, %2;" : "=f"(a), "=f"(b) : "l"(v));
}
__device__ __forceinline__ u64 mul2(u64 a, u64 b) {
    u64 r; asm("mul.rn.f32x2 %0, %1, %2;" : "=l"(r) : "l"(a), "l"(b)); return r;
}
__device__ __forceinline__ void fma2(u64& d, u64 a, u64 b) {
    asm("fma.rn.f32x2 %0, %1, %2, %0;" : "+l"(d) : "l"(a), "l"(b));
}
__device__ __forceinline__ void add2(u64& d, u64 a) {
    asm("add.rn.f32x2 %0, %1, %0;" : "+l"(d) : "l"(a));
}
__device__ __forceinline__ void lds2(u64& a, u64& b, unsigned addr) {
    asm volatile("ld.shared.v2.b64 {%0, %1}, [%2];" : "=l"(a), "=l"(b) : "r"(addr));
}
__device__ __forceinline__ void cpasync16(unsigned dst, const void* src) {
    asm volatile("cp.async.cg.shared.global [%0], [%1], 16;" :: "r"(dst), "l"(src));
}
__device__ __forceinline__ void cpcommit() { asm volatile("cp.async.commit_group;"); }
__device__ __forceinline__ void cpwait0()  { asm volatile("cp.async.wait_group 0;" ::: "memory"); }

// Stage one chunk's W via cp.async with transpose+swizzle scatter (validated R4-R10).
// global [ci][j][n][m16] -> smem [ci][n][j^(n&1)][m16].
__device__ __forceinline__ void stage_W_async(unsigned wbuf, const float* __restrict__ W,
                                              int ch, int tid)
{
    const float* src = W + (size_t)ch * W_FLOATS;
    #pragma unroll
    for (int q = 0; q < 2; q++) {                     // 2048 float4 / 1024 threads
        const int idx = (tid + q * THREADS) * 4;      // float index, 16B granule
        const int ci = idx >> 10;
        const int r  = idx & 1023;
        const int j  = r >> 7;
        const int n  = (r >> 4) & 7;
        const int m  = r & 15;                        // 0,4,8,12
        const unsigned dst = wbuf +
            (unsigned)((ci << 10) + (n << 7) + (((j ^ (n & 1))) << 4) + m) * 4u;
        cpasync16(dst, src + idx);
    }
}

// STAGE: 0 -> uniform-c contraction (no routing); 1,2 -> full routing.
// 1024 threads, 32 warps; each warp owns 2 batches (b0 = warp*2).
template <int STAGE>
__global__ __launch_bounds__(THREADS, 1)
void route_kernel(const float* __restrict__ x, const float* __restrict__ W)
{
    extern __shared__ float sh[];
    float* xs = sh + 2 * W_FLOATS;

    const int tid  = threadIdx.x;
    const int lane = tid & 31;
    const int w    = tid >> 5;      // warp 0..31
    const int j    = lane >> 2;     // out-cap 0..7
    const int mq   = lane & 3;      // m-quad 0..3
    const int b0   = w * 2;         // warp owns batches b0, b0+1
    const int q1   = mq >> 1;       // this lane's owned bb in transposed softmax

    // ---- vsum = sum_{st<STAGE} squash(g_s[st]) for this lane's (2 batches, j, mq) ----
    u64 vp[2][2];
    if (STAGE > 0) {
        #pragma unroll
        for (int bb = 0; bb < 2; bb++) {
            float v0 = 0.f, v1 = 0.f, v2v = 0.f, v3 = 0.f;
            #pragma unroll
            for (int st = 0; st < STAGE; ++st) {
                const float4 s4 = __ldcg(reinterpret_cast<const float4*>(
                    &g_s[st][((b0 + bb) * JCAPS + j) * MDIM + mq * 4]));
                float sq = s4.x * s4.x;
                sq = fmaf(s4.y, s4.y, sq);
                sq = fmaf(s4.z, s4.z, sq);
                sq = fmaf(s4.w, s4.w, sq);
                sq += __shfl_xor_sync(0xffffffffu, sq, 1);
                sq += __shfl_xor_sync(0xffffffffu, sq, 2);   // norm^2 over all 16 m
                const float sc = sqrtf(sq) / (1.0f + sq);    // squash scale
                v0 = fmaf(sc, s4.x, v0); v1 = fmaf(sc, s4.y, v1);
                v2v = fmaf(sc, s4.z, v2v); v3 = fmaf(sc, s4.w, v3);
            }
            vp[bb][0] = pk2(v0, v1);
            vp[bb][1] = pk2(v2v, v3);
        }
    }

    u64 sacc[2][2];
    #pragma unroll
    for (int bb = 0; bb < 2; bb++) { sacc[bb][0] = 0ull; sacc[bb][1] = 0ull; }

    const unsigned shbase = (unsigned)__cvta_generic_to_shared(sh);
    const unsigned xsbase = shbase + 2u * W_FLOATS * 4u;
    const unsigned wofs_e = (unsigned)((j * 16) + mq * 4) * 4u;        // even n
    const unsigned wofs_o = (unsigned)(((j ^ 1) * 16) + mq * 4) * 4u;  // odd n (XOR swizzle)

    // ---- double-buffered-W chunk loop ----
    int ch = blockIdx.x;
    int p  = 0;
    float4 xreg;
    stage_W_async(shbase, W, ch, tid);
    cpcommit();
    {
        const int b = tid >> 4;                        // 1024 threads = 64 b x 16 float4
        const int k = (tid & 15) * 4;
        xreg = __ldcg(reinterpret_cast<const float4*>(
            &x[(size_t)b * (ICAPS * NDIM) + (size_t)ch * (CI * NDIM) + k]));
    }
    bool first = true;

    while (true) {
        if (!first) __syncthreads();
        cpwait0();
        {
            const int b = tid >> 4;
            const int k = (tid & 15) * 4;
            *reinterpret_cast<float4*>(xs + b * X_STRIDE + k) = xreg;
        }
        __syncthreads();

        const int chn = ch + (int)gridDim.x;
        const bool have_next = (chn < NCHUNKS);
        if (have_next) {
            stage_W_async(shbase + (unsigned)(p ^ 1) * (W_FLOATS * 4u), W, chn, tid);
            cpcommit();
            const int b = tid >> 4;
            const int k = (tid & 15) * 4;
            xreg = __ldcg(reinterpret_cast<const float4*>(
                &x[(size_t)b * (ICAPS * NDIM) + (size_t)chn * (CI * NDIM) + k]));
        }

        // ---- compute this chunk (buffer p) ----
        const unsigned wb = shbase + (unsigned)p * (W_FLOATS * 4u);
        const unsigned we = wb + wofs_e;
        const unsigned wo = wb + wofs_o;

        #pragma unroll 1
        for (int ii = 0; ii < CI; ++ii) {
            // Phase 0: x for both bb (broadcast loads)
            float xf[2][8];
            #pragma unroll
            for (int bb = 0; bb < 2; bb++) {
                const unsigned xa = xsbase + (unsigned)((b0 + bb) * X_STRIDE + ii * 8) * 4u;
                u64 t0, t1, t2, t3;
                lds2(t0, t1, xa);
                lds2(t2, t3, xa + 16);
                upk2(t0, xf[bb][0], xf[bb][1]);
                upk2(t1, xf[bb][2], xf[bb][3]);
                upk2(t2, xf[bb][4], xf[bb][5]);
                upk2(t3, xf[bb][6], xf[bb][7]);
            }

            // Phase 1: stream W by n; apply each pair to both bb
            u64 uh[2][2];
            {
                u64 w0, w1;
                lds2(w0, w1, we + (unsigned)(ii * 4096));
                #pragma unroll
                for (int bb = 0; bb < 2; bb++) {
                    const u64 xd = pk2(xf[bb][0], xf[bb][0]);
                    uh[bb][0] = mul2(w0, xd);
                    uh[bb][1] = mul2(w1, xd);
                }
            }
            #pragma unroll
            for (int n = 1; n < 8; n++) {
                u64 w0, w1;
                lds2(w0, w1, ((n & 1) ? wo : we) + (unsigned)(ii * 4096 + n * 512));
                #pragma unroll
                for (int bb = 0; bb < 2; bb++) {
                    const u64 xd = pk2(xf[bb][n], xf[bb][n]);
                    fma2(uh[bb][0], w0, xd);
                    fma2(uh[bb][1], w1, xd);
                }
            }

            if (STAGE == 0) {
                #pragma unroll
                for (int bb = 0; bb < 2; bb++) {
                    add2(sacc[bb][0], uh[bb][0]);
                    add2(sacc[bb][1], uh[bb][1]);
                }
            } else {
                // Phase 2: transposed softmax — lane's q1 bit owns bb = q1.
                float pL[2];
                #pragma unroll
                for (int bb = 0; bb < 2; bb++) {
                    u64 pp = mul2(uh[bb][0], vp[bb][0]);
                    fma2(pp, uh[bb][1], vp[bb][1]);
                    float plo, phi; upk2(pp, plo, phi);
                    pL[bb] = plo + phi;
                }
                // full logit for bb = q1 at this lane's j (3 shfl):
                const float a  = q1 ? pL[1] : pL[0];              // pL[q1]
                const float b_ = q1 ? pL[0] : pL[1];              // pL[1-q1]
                const float s1  = a  + __shfl_xor_sync(0xffffffffu, a, 1);
                const float s1b = b_ + __shfl_xor_sync(0xffffffffu, b_, 1);
                const float t   = s1 + __shfl_xor_sync(0xffffffffu, s1b, 2);
                // one exp + one j-sum + one divide serve both bb
                const float e = __expf(t);            // |logit| < 1: no max needed
                float sm = e;
                sm += __shfl_xor_sync(0xffffffffu, sm, 4);
                sm += __shfl_xor_sync(0xffffffffu, sm, 8);
                sm += __shfl_xor_sync(0xffffffffu, sm, 16);
                const float cm = __fdividef(e, sm);   // c for bb = q1
                const float g  = __shfl_xor_sync(0xffffffffu, cm, 2);   // c for bb = 1-q1
                const float c0 = q1 ? g : cm;
                const float c1 = q1 ? cm : g;
                const u64 c20 = pk2(c0, c0);
                const u64 c21 = pk2(c1, c1);
                fma2(sacc[0][0], c20, uh[0][0]);
                fma2(sacc[0][1], c20, uh[0][1]);
                fma2(sacc[1][0], c21, uh[1][0]);
                fma2(sacc[1][1], c21, uh[1][1]);
            }
        }

        if (!have_next) break;
        ch = chn;
        p ^= 1;
        first = false;
    }

    // ---- flush this warp's disjoint (b, j, mq) partials ----
    const float scale = (STAGE == 0) ? 0.125f : 1.0f;
    float* sout = &g_s[STAGE][0];
    #pragma unroll
    for (int bb = 0; bb < 2; bb++) {
        const int base = ((b0 + bb) * JCAPS + j) * MDIM + mq * 4;
        float a0, a1, a2, a3;
        upk2(sacc[bb][0], a0, a1);
        upk2(sacc[bb][1], a2, a3);
        atomicAdd(&sout[base + 0], scale * a0);
        atomicAdd(&sout[base + 1], scale * a1);
        atomicAdd(&sout[base + 2], scale * a2);
        atomicAdd(&sout[base + 3], scale * a3);
    }
}

// out = squash(s3)
__global__ void final_squash_kernel(float* __restrict__ out)
{
    const int t = blockIdx.x * blockDim.x + threadIdx.x;   // 0..511
    const int b = t >> 3;
    const int j = t & 7;
    const float* sp = &g_s[2][(b * JCAPS + j) * MDIM];
    float sv[MDIM];
    float sn = 0.0f;
    #pragma unroll
    for (int q = 0; q < 4; q++) {
        const float4 tt = __ldcg(reinterpret_cast<const float4*>(sp + q * 4));
        sv[q*4+0] = tt.x; sv[q*4+1] = tt.y; sv[q*4+2] = tt.z; sv[q*4+3] = tt.w;
    }
    #pragma unroll
    for (int m = 0; m < MDIM; m++) sn = fmaf(sv[m], sv[m], sn);
    const float scale = sqrtf(sn) / (1.0f + sn);
    #pragma unroll
    for (int m = 0; m < MDIM; m++) out[(b * JCAPS + j) * MDIM + m] = scale * sv[m];
}

// Tiny dummy to keep ncu's capture slot (-s 5 -c 1) on a route kernel.
__global__ void prof_pad_kernel()
{
    if (threadIdx.x < 32) g_dummy[threadIdx.x] = (float)threadIdx.x;
}

extern "C" void kernel_launch(void* const* d_in, const int* in_sizes, int n_in,
                              void* d_out, int out_size)
{
    const float* x = (const float*)d_in[0];
    const float* W = (const float*)d_in[1];
    if (n_in >= 2 && in_sizes[0] == 8388608 && in_sizes[1] == 4194304) {
        x = (const float*)d_in[1];
        W = (const float*)d_in[0];
    }

    int dev = 0;
    cudaGetDevice(&dev);
    int sm = 148;
    cudaDeviceGetAttribute(&sm, cudaDevAttrMultiProcessorCount, dev);
    if (sm < 1) sm = 1;
    if (sm > 512) sm = 512;

    cudaFuncSetAttribute(route_kernel<0>, cudaFuncAttributeMaxDynamicSharedMemorySize, SMEM_BYTES);
    cudaFuncSetAttribute(route_kernel<1>, cudaFuncAttributeMaxDynamicSharedMemorySize, SMEM_BYTES);
    cudaFuncSetAttribute(route_kernel<2>, cudaFuncAttributeMaxDynamicSharedMemorySize, SMEM_BYTES);

    void* sptr = nullptr;
    cudaGetSymbolAddress(&sptr, g_s);
    cudaMemsetAsync(sptr, 0, sizeof(float) * 3 * BSZ * JCAPS * MDIM);

    prof_pad_kernel<<<1, 32>>>();
    route_kernel<0><<<sm, THREADS, SMEM_BYTES>>>(x, W);
    route_kernel<1><<<sm, THREADS, SMEM_BYTES>>>(x, W);
    route_kernel<2><<<sm, THREADS, SMEM_BYTES>>>(x, W);
    final_squash_kernel<<<16, 32>>>((float*)d_out);
}

// round 12
// speedup vs baseline: 1.9754x; 1.9754x over previous
#include <cuda_runtime.h>

#define BSZ 64
#define ICAPS 8192
#define JCAPS 8
#define NDIM 8
#define MDIM 16

#define CI 8
#define NCHUNKS (ICAPS / CI)       /* 1024 */
#define THREADS 512

#define W_FLOATS (CI * 1024)       /* 8192 per buffer: [ci][n][j^(n&1)][m16] */
#define X_STRIDE 68                /* non-duplicated x row: 64 data + 4 pad */
#define X_FLOATS (BSZ * X_STRIDE)  /* 4352 */
#define SMEM_FLOATS (2 * W_FLOATS + X_FLOATS)       /* 20736 */
#define SMEM_BYTES (SMEM_FLOATS * 4)                /* 82944 B */

__device__ float g_s[3][BSZ * JCAPS * MDIM];   // stage-wise s accumulators
__device__ float g_dummy[32];

typedef unsigned long long u64;

__device__ __forceinline__ u64 pk2(float a, float b) {
    u64 r; asm("mov.b64 %0, {%1, %2};" : "=l"(r) : "f"(a), "f"(b)); return r;
}
__device__ __forceinline__ void upk2(u64 v, float& a, float& b) {
    asm("mov.b64 {%0, %1}, %2;" : "=f"(a), "=f"(b) : "l"(v));
}
__device__ __forceinline__ u64 mul2(u64 a, u64 b) {
    u64 r; asm("mul.rn.f32x2 %0, %1, %2;" : "=l"(r) : "l"(a), "l"(b)); return r;
}
__device__ __forceinline__ void fma2(u64& d, u64 a, u64 b) {
    asm("fma.rn.f32x2 %0, %1, %2, %0;" : "+l"(d) : "l"(a), "l"(b));
}
__device__ __forceinline__ void add2(u64& d, u64 a) {
    asm("add.rn.f32x2 %0, %1, %0;" : "+l"(d) : "l"(a));
}
__device__ __forceinline__ void lds2(u64& a, u64& b, unsigned addr) {
    asm volatile("ld.shared.v2.b64 {%0, %1}, [%2];" : "=l"(a), "=l"(b) : "r"(addr));
}
__device__ __forceinline__ void cpasync16(unsigned dst, const void* src) {
    asm volatile("cp.async.cg.shared.global [%0], [%1], 16;" :: "r"(dst), "l"(src));
}
__device__ __forceinline__ void cpcommit() { asm volatile("cp.async.commit_group;"); }
__device__ __forceinline__ void cpwait0()  { asm volatile("cp.async.wait_group 0;" ::: "memory"); }

// Stage one chunk's W via cp.async with transpose+swizzle scatter (validated R4-R10).
// global [ci][j][n][m16] -> smem [ci][n][j^(n&1)][m16].
__device__ __forceinline__ void stage_W_async(unsigned wbuf, const float* __restrict__ W,
                                              int ch, int tid)
{
    const float* src = W + (size_t)ch * W_FLOATS;
    #pragma unroll
    for (int q = 0; q < 4; q++) {
        const int idx = (tid + q * THREADS) * 4;      // float index, 16B granule
        const int ci = idx >> 10;
        const int r  = idx & 1023;
        const int j  = r >> 7;
        const int n  = (r >> 4) & 7;
        const int m  = r & 15;                        // 0,4,8,12
        const unsigned dst = wbuf +
            (unsigned)((ci << 10) + (n << 7) + (((j ^ (n & 1))) << 4) + m) * 4u;
        cpasync16(dst, src + idx);
    }
}

// u_hat for 4 batches at one (chunk, ii). x loaded in two 4-float halves per bb
// (same lds2 count as R10, half the xf register liveness).
__device__ __forceinline__ void compute_uh4(u64 (&uh)[4][2],
                                            unsigned we, unsigned wo,
                                            unsigned xsbase, int b0, int ii)
{
    float xf[4][4];
    // half A: n = 0..3
    #pragma unroll
    for (int bb = 0; bb < 4; bb++) {
        const unsigned xa = xsbase + (unsigned)((b0 + bb) * X_STRIDE + ii * 8) * 4u;
        u64 t0, t1;
        lds2(t0, t1, xa);                 // broadcast load
        upk2(t0, xf[bb][0], xf[bb][1]);
        upk2(t1, xf[bb][2], xf[bb][3]);
    }
    {
        u64 w0, w1;
        lds2(w0, w1, we + (unsigned)(ii * 4096));
        #pragma unroll
        for (int bb = 0; bb < 4; bb++) {
            const u64 xd = pk2(xf[bb][0], xf[bb][0]);
            uh[bb][0] = mul2(w0, xd);
            uh[bb][1] = mul2(w1, xd);
        }
    }
    #pragma unroll
    for (int n = 1; n < 4; n++) {
        u64 w0, w1;
        lds2(w0, w1, ((n & 1) ? wo : we) + (unsigned)(ii * 4096 + n * 512));
        #pragma unroll
        for (int bb = 0; bb < 4; bb++) {
            const u64 xd = pk2(xf[bb][n], xf[bb][n]);
            fma2(uh[bb][0], w0, xd);
            fma2(uh[bb][1], w1, xd);
        }
    }
    // half B: n = 4..7
    #pragma unroll
    for (int bb = 0; bb < 4; bb++) {
        const unsigned xa = xsbase + (unsigned)((b0 + bb) * X_STRIDE + ii * 8 + 4) * 4u;
        u64 t0, t1;
        lds2(t0, t1, xa);
        upk2(t0, xf[bb][0], xf[bb][1]);
        upk2(t1, xf[bb][2], xf[bb][3]);
    }
    #pragma unroll
    for (int n = 4; n < 8; n++) {
        u64 w0, w1;
        lds2(w0, w1, ((n & 1) ? wo : we) + (unsigned)(ii * 4096 + n * 512));
        #pragma unroll
        for (int bb = 0; bb < 4; bb++) {
            const u64 xd = pk2(xf[bb][n - 4], xf[bb][n - 4]);
            fma2(uh[bb][0], w0, xd);
            fma2(uh[bb][1], w1, xd);
        }
    }
}

// Transposed softmax + accumulate (byte-identical math to validated R10).
__device__ __forceinline__ void softmax_acc4(u64 (&uh)[4][2],
                                             const u64 (&vp)[4][2],
                                             u64 (&sacc)[4][2],
                                             bool q0, bool q1)
{
    float pL[4];
    #pragma unroll
    for (int bb = 0; bb < 4; bb++) {
        u64 pp = mul2(uh[bb][0], vp[bb][0]);
        fma2(pp, uh[bb][1], vp[bb][1]);
        float plo, phi; upk2(pp, plo, phi);
        pL[bb] = plo + phi;
    }
    const float pm   = q1 ? (q0 ? pL[3] : pL[2]) : (q0 ? pL[1] : pL[0]); // p[mq]
    const float pmx1 = q1 ? (q0 ? pL[2] : pL[3]) : (q0 ? pL[0] : pL[1]); // p[mq^1]
    const float pmx2 = q1 ? (q0 ? pL[1] : pL[0]) : (q0 ? pL[3] : pL[2]); // p[mq^2]
    const float pmx3 = q1 ? (q0 ? pL[0] : pL[1]) : (q0 ? pL[2] : pL[3]); // p[mq^3]
    const float SA = pm   + __shfl_xor_sync(0xffffffffu, pmx1, 1);
    const float SB = pmx2 + __shfl_xor_sync(0xffffffffu, pmx3, 1);
    const float t  = SA + __shfl_xor_sync(0xffffffffu, SB, 2);  // full logit, bb = mq
    const float e = __expf(t);            // |logit| < 1: no max needed
    float sm = e;
    sm += __shfl_xor_sync(0xffffffffu, sm, 4);
    sm += __shfl_xor_sync(0xffffffffu, sm, 8);
    sm += __shfl_xor_sync(0xffffffffu, sm, 16);
    const float cm = __fdividef(e, sm);   // c for bb = mq
    const float g  = __shfl_xor_sync(0xffffffffu, cm, 2);
    const float cA = q1 ? g : cm;
    const float cB = q1 ? cm : g;
    const float gA = __shfl_xor_sync(0xffffffffu, cA, 1);
    const float gB = __shfl_xor_sync(0xffffffffu, cB, 1);
    float cc[4];
    cc[0] = q0 ? gA : cA;
    cc[1] = q0 ? cA : gA;
    cc[2] = q0 ? gB : cB;
    cc[3] = q0 ? cB : gB;
    #pragma unroll
    for (int bb = 0; bb < 4; bb++) {
        const u64 c2 = pk2(cc[bb], cc[bb]);
        fma2(sacc[bb][0], c2, uh[bb][0]);
        fma2(sacc[bb][1], c2, uh[bb][1]);
    }
}

// STAGE: 0 -> uniform-c contraction (no routing); 1,2 -> full routing.
template <int STAGE>
__global__ __launch_bounds__(THREADS, 1)
void route_kernel(const float* __restrict__ x, const float* __restrict__ W)
{
    extern __shared__ float sh[];
    float* xs = sh + 2 * W_FLOATS;

    const int tid  = threadIdx.x;
    const int lane = tid & 31;
    const int w    = tid >> 5;
    const int j    = lane >> 2;     // out-cap 0..7
    const int mq   = lane & 3;      // m-quad 0..3
    const int b0   = w * 4;         // warp owns batches b0..b0+3
    const bool q0  = (mq & 1) != 0;
    const bool q1  = (mq & 2) != 0;

    // ---- vsum = sum_{st<STAGE} squash(g_s[st]) for this lane's (4 batches, j, mq) ----
    u64 vp[4][2];
    if (STAGE > 0) {
        #pragma unroll
        for (int bb = 0; bb < 4; bb++) {
            float v0 = 0.f, v1 = 0.f, v2v = 0.f, v3 = 0.f;
            #pragma unroll
            for (int st = 0; st < STAGE; ++st) {
                const float4 s4 = __ldcg(reinterpret_cast<const float4*>(
                    &g_s[st][((b0 + bb) * JCAPS + j) * MDIM + mq * 4]));
                float sq = s4.x * s4.x;
                sq = fmaf(s4.y, s4.y, sq);
                sq = fmaf(s4.z, s4.z, sq);
                sq = fmaf(s4.w, s4.w, sq);
                sq += __shfl_xor_sync(0xffffffffu, sq, 1);
                sq += __shfl_xor_sync(0xffffffffu, sq, 2);   // norm^2 over all 16 m
                const float sc = sqrtf(sq) / (1.0f + sq);    // squash scale
                v0 = fmaf(sc, s4.x, v0); v1 = fmaf(sc, s4.y, v1);
                v2v = fmaf(sc, s4.z, v2v); v3 = fmaf(sc, s4.w, v3);
            }
            vp[bb][0] = pk2(v0, v1);
            vp[bb][1] = pk2(v2v, v3);
        }
    }

    u64 sacc[4][2];
    #pragma unroll
    for (int bb = 0; bb < 4; bb++) { sacc[bb][0] = 0ull; sacc[bb][1] = 0ull; }

    const unsigned shbase = (unsigned)__cvta_generic_to_shared(sh);
    const unsigned xsbase = shbase + 2u * W_FLOATS * 4u;
    const unsigned wofs_e = (unsigned)((j * 16) + mq * 4) * 4u;        // even n
    const unsigned wofs_o = (unsigned)(((j ^ 1) * 16) + mq * 4) * 4u;  // odd n (XOR swizzle)

    // ---- double-buffered-W chunk loop (identical to validated R8-R10) ----
    int ch = blockIdx.x;
    int p  = 0;
    float4 xreg[2];
    stage_W_async(shbase, W, ch, tid);
    cpcommit();
    #pragma unroll
    for (int q = 0; q < 2; q++) {
        const int idx4 = tid + q * THREADS;
        const int b = idx4 >> 4;
        const int k = (idx4 & 15) * 4;
        xreg[q] = __ldcg(reinterpret_cast<const float4*>(
            &x[(size_t)b * (ICAPS * NDIM) + (size_t)ch * (CI * NDIM) + k]));
    }
    bool first = true;

    while (true) {
        if (!first) __syncthreads();
        cpwait0();
        #pragma unroll
        for (int q = 0; q < 2; q++) {
            const int idx4 = tid + q * THREADS;
            const int b = idx4 >> 4;
            const int k = (idx4 & 15) * 4;
            *reinterpret_cast<float4*>(xs + b * X_STRIDE + k) = xreg[q];
        }
        __syncthreads();

        const int chn = ch + (int)gridDim.x;
        const bool have_next = (chn < NCHUNKS);
        if (have_next) {
            stage_W_async(shbase + (unsigned)(p ^ 1) * (W_FLOATS * 4u), W, chn, tid);
            cpcommit();
            #pragma unroll
            for (int q = 0; q < 2; q++) {
                const int idx4 = tid + q * THREADS;
                const int b = idx4 >> 4;
                const int k = (idx4 & 15) * 4;
                xreg[q] = __ldcg(reinterpret_cast<const float4*>(
                    &x[(size_t)b * (ICAPS * NDIM) + (size_t)chn * (CI * NDIM) + k]));
            }
        }

        // ---- compute this chunk (buffer p) ----
        const unsigned wb = shbase + (unsigned)p * (W_FLOATS * 4u);
        const unsigned we = wb + wofs_e;
        const unsigned wo = wb + wofs_o;

        if (STAGE == 0) {
            #pragma unroll 1
            for (int ii = 0; ii < CI; ++ii) {
                u64 uh[4][2];
                compute_uh4(uh, we, wo, xsbase, b0, ii);
                #pragma unroll
                for (int bb = 0; bb < 4; bb++) {
                    add2(sacc[bb][0], uh[bb][0]);
                    add2(sacc[bb][1], uh[bb][1]);
                }
            }
        } else {
            // Software-pipelined: softmax(prev ii) overlaps compute_uh(next ii).
            u64 uhA[4][2], uhB[4][2];
            compute_uh4(uhA, we, wo, xsbase, b0, 0);
            #pragma unroll 1
            for (int t = 0; t < 3; t++) {            // covers ii = 1..6
                compute_uh4(uhB, we, wo, xsbase, b0, 2 * t + 1);
                softmax_acc4(uhA, vp, sacc, q0, q1);
                compute_uh4(uhA, we, wo, xsbase, b0, 2 * t + 2);
                softmax_acc4(uhB, vp, sacc, q0, q1);
            }
            compute_uh4(uhB, we, wo, xsbase, b0, 7);
            softmax_acc4(uhA, vp, sacc, q0, q1);
            softmax_acc4(uhB, vp, sacc, q0, q1);
        }

        if (!have_next) break;
        ch = chn;
        p ^= 1;
        first = false;
    }

    // ---- flush this warp's disjoint (b, j, mq) partials ----
    const float scale = (STAGE == 0) ? 0.125f : 1.0f;
    float* sout = &g_s[STAGE][0];
    #pragma unroll
    for (int bb = 0; bb < 4; bb++) {
        const int base = ((b0 + bb) * JCAPS + j) * MDIM + mq * 4;
        float a0, a1, a2, a3;
        upk2(sacc[bb][0], a0, a1);
        upk2(sacc[bb][1], a2, a3);
        atomicAdd(&sout[base + 0], scale * a0);
        atomicAdd(&sout[base + 1], scale * a1);
        atomicAdd(&sout[base + 2], scale * a2);
        atomicAdd(&sout[base + 3], scale * a3);
    }
}

// out = squash(s3)
__global__ void final_squash_kernel(float* __restrict__ out)
{
    const int t = blockIdx.x * blockDim.x + threadIdx.x;   // 0..511
    const int b = t >> 3;
    const int j = t & 7;
    const float* sp = &g_s[2][(b * JCAPS + j) * MDIM];
    float sv[MDIM];
    float sn = 0.0f;
    #pragma unroll
    for (int q = 0; q < 4; q++) {
        const float4 tt = __ldcg(reinterpret_cast<const float4*>(sp + q * 4));
        sv[q*4+0] = tt.x; sv[q*4+1] = tt.y; sv[q*4+2] = tt.z; sv[q*4+3] = tt.w;
    }
    #pragma unroll
    for (int m = 0; m < MDIM; m++) sn = fmaf(sv[m], sv[m], sn);
    const float scale = sqrtf(sn) / (1.0f + sn);
    #pragma unroll
    for (int m = 0; m < MDIM; m++) out[(b * JCAPS + j) * MDIM + m] = scale * sv[m];
}

// Tiny dummy to keep ncu's capture slot (-s 5 -c 1) on a route kernel.
__global__ void prof_pad_kernel()
{
    if (threadIdx.x < 32) g_dummy[threadIdx.x] = (float)threadIdx.x;
}

extern "C" void kernel_launch(void* const* d_in, const int* in_sizes, int n_in,
                              void* d_out, int out_size)
{
    const float* x = (const float*)d_in[0];
    const float* W = (const float*)d_in[1];
    if (n_in >= 2 && in_sizes[0] == 8388608 && in_sizes[1] == 4194304) {
        x = (const float*)d_in[1];
        W = (const float*)d_in[0];
    }

    int dev = 0;
    cudaGetDevice(&dev);
    int sm = 148;
    cudaDeviceGetAttribute(&sm, cudaDevAttrMultiProcessorCount, dev);
    if (sm < 1) sm = 1;
    if (sm > 512) sm = 512;

    cudaFuncSetAttribute(route_kernel<0>, cudaFuncAttributeMaxDynamicSharedMemorySize, SMEM_BYTES);
    cudaFuncSetAttribute(route_kernel<1>, cudaFuncAttributeMaxDynamicSharedMemorySize, SMEM_BYTES);
    cudaFuncSetAttribute(route_kernel<2>, cudaFuncAttributeMaxDynamicSharedMemorySize, SMEM_BYTES);

    void* sptr = nullptr;
    cudaGetSymbolAddress(&sptr, g_s);
    cudaMemsetAsync(sptr, 0, sizeof(float) * 3 * BSZ * JCAPS * MDIM);

    prof_pad_kernel<<<1, 32>>>();
    route_kernel<0><<<sm, THREADS, SMEM_BYTES>>>(x, W);
    route_kernel<1><<<sm, THREADS, SMEM_BYTES>>>(x, W);
    route_kernel<2><<<sm, THREADS, SMEM_BYTES>>>(x, W);
    final_squash_kernel<<<16, 32>>>((float*)d_out);
}

// round 13
// speedup vs baseline: 1.9976x; 1.0112x over previous
#include <cuda_runtime.h>

#define BSZ 64
#define ICAPS 8192
#define JCAPS 8
#define NDIM 8
#define MDIM 16

#define CI 8
#define NCHUNKS (ICAPS / CI)       /* 1024 */
#define THREADS 512

#define W_FLOATS (CI * 1024)       /* 8192 per buffer: [ci][n][j^(n&1)][m16] */
#define X_STRIDE 68                /* non-duplicated x row: 64 data + 4 pad */
#define X_FLOATS (BSZ * X_STRIDE)  /* 4352 */
#define SMEM_FLOATS (2 * W_FLOATS + X_FLOATS)       /* 20736 */
#define SMEM_BYTES (SMEM_FLOATS * 4)                /* 82944 B */

__device__ float g_s[3][BSZ * JCAPS * MDIM];   // stage-wise s accumulators
__device__ float g_dummy[32];

typedef unsigned long long u64;

__device__ __forceinline__ u64 pk2(float a, float b) {
    u64 r; asm("mov.b64 %0, {%1, %2};" : "=l"(r) : "f"(a), "f"(b)); return r;
}
__device__ __forceinline__ void upk2(u64 v, float& a, float& b) {
    asm("mov.b64 {%0, %1}, %2;" : "=f"(a), "=f"(b) : "l"(v));
}
__device__ __forceinline__ u64 mul2(u64 a, u64 b) {
    u64 r; asm("mul.rn.f32x2 %0, %1, %2;" : "=l"(r) : "l"(a), "l"(b)); return r;
}
__device__ __forceinline__ void fma2(u64& d, u64 a, u64 b) {
    asm("fma.rn.f32x2 %0, %1, %2, %0;" : "+l"(d) : "l"(a), "l"(b));
}
__device__ __forceinline__ void lds2(u64& a, u64& b, unsigned addr) {
    asm volatile("ld.shared.v2.b64 {%0, %1}, [%2];" : "=l"(a), "=l"(b) : "r"(addr));
}
__device__ __forceinline__ void cpasync16(unsigned dst, const void* src) {
    asm volatile("cp.async.cg.shared.global [%0], [%1], 16;" :: "r"(dst), "l"(src));
}
__device__ __forceinline__ void cpcommit() { asm volatile("cp.async.commit_group;"); }
__device__ __forceinline__ void cpwait0()  { asm volatile("cp.async.wait_group 0;" ::: "memory"); }

// Stage one chunk's W via cp.async with transpose+swizzle scatter (validated R4-R12).
// global [ci][j][n][m16] -> smem [ci][n][j^(n&1)][m16].
__device__ __forceinline__ void stage_W_async(unsigned wbuf, const float* __restrict__ W,
                                              int ch, int tid)
{
    const float* src = W + (size_t)ch * W_FLOATS;
    #pragma unroll
    for (int q = 0; q < 4; q++) {
        const int idx = (tid + q * THREADS) * 4;      // float index, 16B granule
        const int ci = idx >> 10;
        const int r  = idx & 1023;
        const int j  = r >> 7;
        const int n  = (r >> 4) & 7;
        const int m  = r & 15;                        // 0,4,8,12
        const unsigned dst = wbuf +
            (unsigned)((ci << 10) + (n << 7) + (((j ^ (n & 1))) << 4) + m) * 4u;
        cpasync16(dst, src + idx);
    }
}

// u_hat for 4 batches at one (chunk, ii). (validated R12)
__device__ __forceinline__ void compute_uh4(u64 (&uh)[4][2],
                                            unsigned we, unsigned wo,
                                            unsigned xsbase, int b0, int ii)
{
    float xf[4][4];
    // half A: n = 0..3
    #pragma unroll
    for (int bb = 0; bb < 4; bb++) {
        const unsigned xa = xsbase + (unsigned)((b0 + bb) * X_STRIDE + ii * 8) * 4u;
        u64 t0, t1;
        lds2(t0, t1, xa);                 // broadcast load
        upk2(t0, xf[bb][0], xf[bb][1]);
        upk2(t1, xf[bb][2], xf[bb][3]);
    }
    {
        u64 w0, w1;
        lds2(w0, w1, we + (unsigned)(ii * 4096));
        #pragma unroll
        for (int bb = 0; bb < 4; bb++) {
            const u64 xd = pk2(xf[bb][0], xf[bb][0]);
            uh[bb][0] = mul2(w0, xd);
            uh[bb][1] = mul2(w1, xd);
        }
    }
    #pragma unroll
    for (int n = 1; n < 4; n++) {
        u64 w0, w1;
        lds2(w0, w1, ((n & 1) ? wo : we) + (unsigned)(ii * 4096 + n * 512));
        #pragma unroll
        for (int bb = 0; bb < 4; bb++) {
            const u64 xd = pk2(xf[bb][n], xf[bb][n]);
            fma2(uh[bb][0], w0, xd);
            fma2(uh[bb][1], w1, xd);
        }
    }
    // half B: n = 4..7
    #pragma unroll
    for (int bb = 0; bb < 4; bb++) {
        const unsigned xa = xsbase + (unsigned)((b0 + bb) * X_STRIDE + ii * 8 + 4) * 4u;
        u64 t0, t1;
        lds2(t0, t1, xa);
        upk2(t0, xf[bb][0], xf[bb][1]);
        upk2(t1, xf[bb][2], xf[bb][3]);
    }
    #pragma unroll
    for (int n = 4; n < 8; n++) {
        u64 w0, w1;
        lds2(w0, w1, ((n & 1) ? wo : we) + (unsigned)(ii * 4096 + n * 512));
        #pragma unroll
        for (int bb = 0; bb < 4; bb++) {
            const u64 xd = pk2(xf[bb][n - 4], xf[bb][n - 4]);
            fma2(uh[bb][0], w0, xd);
            fma2(uh[bb][1], w1, xd);
        }
    }
}

// Stage-0: accumulate W.x directly into sacc (no uh temp, no add2).
__device__ __forceinline__ void accum_direct4(u64 (&sacc)[4][2],
                                              unsigned we, unsigned wo,
                                              unsigned xsbase, int b0, int ii)
{
    float xf[4][4];
    #pragma unroll
    for (int bb = 0; bb < 4; bb++) {
        const unsigned xa = xsbase + (unsigned)((b0 + bb) * X_STRIDE + ii * 8) * 4u;
        u64 t0, t1;
        lds2(t0, t1, xa);
        upk2(t0, xf[bb][0], xf[bb][1]);
        upk2(t1, xf[bb][2], xf[bb][3]);
    }
    #pragma unroll
    for (int n = 0; n < 4; n++) {
        u64 w0, w1;
        lds2(w0, w1, ((n & 1) ? wo : we) + (unsigned)(ii * 4096 + n * 512));
        #pragma unroll
        for (int bb = 0; bb < 4; bb++) {
            const u64 xd = pk2(xf[bb][n], xf[bb][n]);
            fma2(sacc[bb][0], w0, xd);
            fma2(sacc[bb][1], w1, xd);
        }
    }
    #pragma unroll
    for (int bb = 0; bb < 4; bb++) {
        const unsigned xa = xsbase + (unsigned)((b0 + bb) * X_STRIDE + ii * 8 + 4) * 4u;
        u64 t0, t1;
        lds2(t0, t1, xa);
        upk2(t0, xf[bb][0], xf[bb][1]);
        upk2(t1, xf[bb][2], xf[bb][3]);
    }
    #pragma unroll
    for (int n = 4; n < 8; n++) {
        u64 w0, w1;
        lds2(w0, w1, ((n & 1) ? wo : we) + (unsigned)(ii * 4096 + n * 512));
        #pragma unroll
        for (int bb = 0; bb < 4; bb++) {
            const u64 xd = pk2(xf[bb][n - 4], xf[bb][n - 4]);
            fma2(sacc[bb][0], w0, xd);
            fma2(sacc[bb][1], w1, xd);
        }
    }
}

// Batched-2 transposed softmax + accumulate: two independent chains interleaved.
// Per-softmax math byte-identical to validated R10/R12.
__device__ __forceinline__ void softmax2_acc4(const u64 (&uhA)[4][2], const u64 (&uhB)[4][2],
                                              const u64 (&vp)[4][2],
                                              u64 (&sacc)[4][2],
                                              bool q0, bool q1)
{
    float pLa[4], pLb[4];
    #pragma unroll
    for (int bb = 0; bb < 4; bb++) {
        u64 pa = mul2(uhA[bb][0], vp[bb][0]);
        fma2(pa, uhA[bb][1], vp[bb][1]);
        float lo, hi; upk2(pa, lo, hi);
        pLa[bb] = lo + hi;
        u64 pb = mul2(uhB[bb][0], vp[bb][0]);
        fma2(pb, uhB[bb][1], vp[bb][1]);
        upk2(pb, lo, hi);
        pLb[bb] = lo + hi;
    }
    const float pmA   = q1 ? (q0 ? pLa[3] : pLa[2]) : (q0 ? pLa[1] : pLa[0]);
    const float pmx1A = q1 ? (q0 ? pLa[2] : pLa[3]) : (q0 ? pLa[0] : pLa[1]);
    const float pmx2A = q1 ? (q0 ? pLa[1] : pLa[0]) : (q0 ? pLa[3] : pLa[2]);
    const float pmx3A = q1 ? (q0 ? pLa[0] : pLa[1]) : (q0 ? pLa[2] : pLa[3]);
    const float pmB   = q1 ? (q0 ? pLb[3] : pLb[2]) : (q0 ? pLb[1] : pLb[0]);
    const float pmx1B = q1 ? (q0 ? pLb[2] : pLb[3]) : (q0 ? pLb[0] : pLb[1]);
    const float pmx2B = q1 ? (q0 ? pLb[1] : pLb[0]) : (q0 ? pLb[3] : pLb[2]);
    const float pmx3B = q1 ? (q0 ? pLb[0] : pLb[1]) : (q0 ? pLb[2] : pLb[3]);

    const float SAa = pmA   + __shfl_xor_sync(0xffffffffu, pmx1A, 1);
    const float SAb = pmB   + __shfl_xor_sync(0xffffffffu, pmx1B, 1);
    const float SBa = pmx2A + __shfl_xor_sync(0xffffffffu, pmx3A, 1);
    const float SBb = pmx2B + __shfl_xor_sync(0xffffffffu, pmx3B, 1);
    const float ta  = SAa + __shfl_xor_sync(0xffffffffu, SBa, 2);   // full logit, bb = mq
    const float tb  = SAb + __shfl_xor_sync(0xffffffffu, SBb, 2);

    const float ea = __expf(ta);          // |logit| < 1: no max needed
    const float eb = __expf(tb);
    float sma = ea, smb = eb;
    sma += __shfl_xor_sync(0xffffffffu, sma, 4);
    smb += __shfl_xor_sync(0xffffffffu, smb, 4);
    sma += __shfl_xor_sync(0xffffffffu, sma, 8);
    smb += __shfl_xor_sync(0xffffffffu, smb, 8);
    sma += __shfl_xor_sync(0xffffffffu, sma, 16);
    smb += __shfl_xor_sync(0xffffffffu, smb, 16);
    const float cma = __fdividef(ea, sma);
    const float cmb = __fdividef(eb, smb);

    const float ga  = __shfl_xor_sync(0xffffffffu, cma, 2);
    const float gb  = __shfl_xor_sync(0xffffffffu, cmb, 2);
    const float cAa = q1 ? ga : cma;
    const float cBa = q1 ? cma : ga;
    const float cAb = q1 ? gb : cmb;
    const float cBb = q1 ? cmb : gb;
    const float gAa = __shfl_xor_sync(0xffffffffu, cAa, 1);
    const float gBa = __shfl_xor_sync(0xffffffffu, cBa, 1);
    const float gAb = __shfl_xor_sync(0xffffffffu, cAb, 1);
    const float gBb = __shfl_xor_sync(0xffffffffu, cBb, 1);
    float cca[4], ccb[4];
    cca[0] = q0 ? gAa : cAa;  cca[1] = q0 ? cAa : gAa;
    cca[2] = q0 ? gBa : cBa;  cca[3] = q0 ? cBa : gBa;
    ccb[0] = q0 ? gAb : cAb;  ccb[1] = q0 ? cAb : gAb;
    ccb[2] = q0 ? gBb : cBb;  ccb[3] = q0 ? cBb : gBb;
    #pragma unroll
    for (int bb = 0; bb < 4; bb++) {
        const u64 c2a = pk2(cca[bb], cca[bb]);
        fma2(sacc[bb][0], c2a, uhA[bb][0]);
        fma2(sacc[bb][1], c2a, uhA[bb][1]);
        const u64 c2b = pk2(ccb[bb], ccb[bb]);
        fma2(sacc[bb][0], c2b, uhB[bb][0]);
        fma2(sacc[bb][1], c2b, uhB[bb][1]);
    }
}

// STAGE: 0 -> uniform-c contraction (no routing); 1,2 -> full routing.
template <int STAGE>
__global__ __launch_bounds__(THREADS, 1)
void route_kernel(const float* __restrict__ x, const float* __restrict__ W)
{
    extern __shared__ float sh[];
    float* xs = sh + 2 * W_FLOATS;

    const int tid  = threadIdx.x;
    const int lane = tid & 31;
    const int w    = tid >> 5;
    const int j    = lane >> 2;     // out-cap 0..7
    const int mq   = lane & 3;      // m-quad 0..3
    const int b0   = w * 4;         // warp owns batches b0..b0+3
    const bool q0  = (mq & 1) != 0;
    const bool q1  = (mq & 2) != 0;

    // ---- vsum = sum_{st<STAGE} squash(g_s[st]) for this lane's (4 batches, j, mq) ----
    u64 vp[4][2];
    if (STAGE > 0) {
        #pragma unroll
        for (int bb = 0; bb < 4; bb++) {
            float v0 = 0.f, v1 = 0.f, v2v = 0.f, v3 = 0.f;
            #pragma unroll
            for (int st = 0; st < STAGE; ++st) {
                const float4 s4 = __ldcg(reinterpret_cast<const float4*>(
                    &g_s[st][((b0 + bb) * JCAPS + j) * MDIM + mq * 4]));
                float sq = s4.x * s4.x;
                sq = fmaf(s4.y, s4.y, sq);
                sq = fmaf(s4.z, s4.z, sq);
                sq = fmaf(s4.w, s4.w, sq);
                sq += __shfl_xor_sync(0xffffffffu, sq, 1);
                sq += __shfl_xor_sync(0xffffffffu, sq, 2);   // norm^2 over all 16 m
                const float sc = sqrtf(sq) / (1.0f + sq);    // squash scale
                v0 = fmaf(sc, s4.x, v0); v1 = fmaf(sc, s4.y, v1);
                v2v = fmaf(sc, s4.z, v2v); v3 = fmaf(sc, s4.w, v3);
            }
            vp[bb][0] = pk2(v0, v1);
            vp[bb][1] = pk2(v2v, v3);
        }
    }

    u64 sacc[4][2];
    #pragma unroll
    for (int bb = 0; bb < 4; bb++) { sacc[bb][0] = 0ull; sacc[bb][1] = 0ull; }

    const unsigned shbase = (unsigned)__cvta_generic_to_shared(sh);
    const unsigned xsbase = shbase + 2u * W_FLOATS * 4u;
    const unsigned wofs_e = (unsigned)((j * 16) + mq * 4) * 4u;        // even n
    const unsigned wofs_o = (unsigned)(((j ^ 1) * 16) + mq * 4) * 4u;  // odd n (XOR swizzle)

    // ---- double-buffered-W chunk loop (identical to validated R8-R12) ----
    int ch = blockIdx.x;
    int p  = 0;
    float4 xreg[2];
    stage_W_async(shbase, W, ch, tid);
    cpcommit();
    #pragma unroll
    for (int q = 0; q < 2; q++) {
        const int idx4 = tid + q * THREADS;
        const int b = idx4 >> 4;
        const int k = (idx4 & 15) * 4;
        xreg[q] = __ldcg(reinterpret_cast<const float4*>(
            &x[(size_t)b * (ICAPS * NDIM) + (size_t)ch * (CI * NDIM) + k]));
    }
    bool first = true;

    while (true) {
        if (!first) __syncthreads();
        cpwait0();
        #pragma unroll
        for (int q = 0; q < 2; q++) {
            const int idx4 = tid + q * THREADS;
            const int b = idx4 >> 4;
            const int k = (idx4 & 15) * 4;
            *reinterpret_cast<float4*>(xs + b * X_STRIDE + k) = xreg[q];
        }
        __syncthreads();

        const int chn = ch + (int)gridDim.x;
        const bool have_next = (chn < NCHUNKS);
        if (have_next) {
            stage_W_async(shbase + (unsigned)(p ^ 1) * (W_FLOATS * 4u), W, chn, tid);
            cpcommit();
            #pragma unroll
            for (int q = 0; q < 2; q++) {
                const int idx4 = tid + q * THREADS;
                const int b = idx4 >> 4;
                const int k = (idx4 & 15) * 4;
                xreg[q] = __ldcg(reinterpret_cast<const float4*>(
                    &x[(size_t)b * (ICAPS * NDIM) + (size_t)chn * (CI * NDIM) + k]));
            }
        }

        // ---- compute this chunk (buffer p) ----
        const unsigned wb = shbase + (unsigned)p * (W_FLOATS * 4u);
        const unsigned we = wb + wofs_e;
        const unsigned wo = wb + wofs_o;

        if (STAGE == 0) {
            #pragma unroll 1
            for (int ii = 0; ii < CI; ++ii)
                accum_direct4(sacc, we, wo, xsbase, b0, ii);
        } else {
            // Batched-2 softmax: two chains per traversal, fully unrolled chunk body.
            u64 uhA[4][2], uhB[4][2];
            #pragma unroll
            for (int t = 0; t < 4; t++) {
                compute_uh4(uhA, we, wo, xsbase, b0, 2 * t);
                compute_uh4(uhB, we, wo, xsbase, b0, 2 * t + 1);
                softmax2_acc4(uhA, uhB, vp, sacc, q0, q1);
            }
        }

        if (!have_next) break;
        ch = chn;
        p ^= 1;
        first = false;
    }

    // ---- flush this warp's disjoint (b, j, mq) partials ----
    const float scale = (STAGE == 0) ? 0.125f : 1.0f;
    float* sout = &g_s[STAGE][0];
    #pragma unroll
    for (int bb = 0; bb < 4; bb++) {
        const int base = ((b0 + bb) * JCAPS + j) * MDIM + mq * 4;
        float a0, a1, a2, a3;
        upk2(sacc[bb][0], a0, a1);
        upk2(sacc[bb][1], a2, a3);
        atomicAdd(&sout[base + 0], scale * a0);
        atomicAdd(&sout[base + 1], scale * a1);
        atomicAdd(&sout[base + 2], scale * a2);
        atomicAdd(&sout[base + 3], scale * a3);
    }
}

// out = squash(s3)
__global__ void final_squash_kernel(float* __restrict__ out)
{
    const int t = blockIdx.x * blockDim.x + threadIdx.x;   // 0..511
    const int b = t >> 3;
    const int j = t & 7;
    const float* sp = &g_s[2][(b * JCAPS + j) * MDIM];
    float sv[MDIM];
    float sn = 0.0f;
    #pragma unroll
    for (int q = 0; q < 4; q++) {
        const float4 tt = __ldcg(reinterpret_cast<const float4*>(sp + q * 4));
        sv[q*4+0] = tt.x; sv[q*4+1] = tt.y; sv[q*4+2] = tt.z; sv[q*4+3] = tt.w;
    }
    #pragma unroll
    for (int m = 0; m < MDIM; m++) sn = fmaf(sv[m], sv[m], sn);
    const float scale = sqrtf(sn) / (1.0f + sn);
    #pragma unroll
    for (int m = 0; m < MDIM; m++) out[(b * JCAPS + j) * MDIM + m] = scale * sv[m];
}

// Tiny dummy to keep ncu's capture slot (-s 5 -c 1) on a route kernel.
__global__ void prof_pad_kernel()
{
    if (threadIdx.x < 32) g_dummy[threadIdx.x] = (float)threadIdx.x;
}

extern "C" void kernel_launch(void* const* d_in, const int* in_sizes, int n_in,
                              void* d_out, int out_size)
{
    const float* x = (const float*)d_in[0];
    const float* W = (const float*)d_in[1];
    if (n_in >= 2 && in_sizes[0] == 8388608 && in_sizes[1] == 4194304) {
        x = (const float*)d_in[1];
        W = (const float*)d_in[0];
    }

    int dev = 0;
    cudaGetDevice(&dev);
    int sm = 148;
    cudaDeviceGetAttribute(&sm, cudaDevAttrMultiProcessorCount, dev);
    if (sm < 1) sm = 1;
    if (sm > 512) sm = 512;

    cudaFuncSetAttribute(route_kernel<0>, cudaFuncAttributeMaxDynamicSharedMemorySize, SMEM_BYTES);
    cudaFuncSetAttribute(route_kernel<1>, cudaFuncAttributeMaxDynamicSharedMemorySize, SMEM_BYTES);
    cudaFuncSetAttribute(route_kernel<2>, cudaFuncAttributeMaxDynamicSharedMemorySize, SMEM_BYTES);

    void* sptr = nullptr;
    cudaGetSymbolAddress(&sptr, g_s);
    cudaMemsetAsync(sptr, 0, sizeof(float) * 3 * BSZ * JCAPS * MDIM);

    prof_pad_kernel<<<1, 32>>>();
    route_kernel<0><<<sm, THREADS, SMEM_BYTES>>>(x, W);
    route_kernel<1><<<sm, THREADS, SMEM_BYTES>>>(x, W);
    route_kernel<2><<<sm, THREADS, SMEM_BYTES>>>(x, W);
    final_squash_kernel<<<16, 32>>>((float*)d_out);
}